// round 13
// baseline (speedup 1.0000x reference)
#include <cuda_runtime.h>
#include <cstdint>

#define NFEAT 20000
#define DOUT  256
#define BATCH 4096
#define KD    64

// ---------------- scratch (static device globals; no runtime allocation) ----
__device__ float g_Z[(size_t)DOUT * NFEAT];              // zpre[d][n]
__device__ unsigned long long g_pack[DOUT * 256];        // (f2o(val)<<32)|idx, desc per row
__device__ int   g_sel[DOUT];                            // selected column per row d

// orderable-uint mapping for floats (monotone increasing)
__device__ __forceinline__ uint32_t f2o(float f) {
    uint32_t b = __float_as_uint(f);
    return (b & 0x80000000u) ? ~b : (b | 0x80000000u);
}
__device__ __forceinline__ float o2f(uint32_t m) {
    uint32_t b = (m & 0x80000000u) ? (m & 0x7fffffffu) : ~m;
    return __uint_as_float(b);
}

// ---------------- FFMA-only transcendentals (no MUFU, ~1-2 ulp) -------------
__device__ __forceinline__ float fast_log(float x) {      // x normal, > 0
    int i = __float_as_int(x);
    int e = (i - 0x3f3504f3) & 0xff800000;
    float m = __int_as_float(i - e);
    float fe = (float)(e >> 23);
    float f = m - 1.0f;
    float z = f * f;
    float p = 7.0376836292e-2f;
    p = fmaf(p, f, -1.1514610310e-1f);
    p = fmaf(p, f,  1.1676998740e-1f);
    p = fmaf(p, f, -1.2420140846e-1f);
    p = fmaf(p, f,  1.4249322787e-1f);
    p = fmaf(p, f, -1.6668057665e-1f);
    p = fmaf(p, f,  2.0000714765e-1f);
    p = fmaf(p, f, -2.4999993993e-1f);
    p = fmaf(p, f,  3.3333331174e-1f);
    float y = p * f * z;
    y = fmaf(fe, -2.12194440e-4f, y);
    y = fmaf(-0.5f, z, y);
    float r = f + y;
    return fmaf(fe, 0.693359375f, r);
}

__device__ __forceinline__ float fast_exp(float x) {      // |x| < ~80
    const float LOG2E = 1.4426950408889634f;
    float fr = fmaf(x, LOG2E, 12582912.0f);
    int ti = __float_as_int(fr) - 0x4B400000;
    float r = fr - 12582912.0f;
    float f = fmaf(r, -0.693359375f, x);
    f = fmaf(r, 2.12194440e-4f, f);
    float p = 1.9875691500e-4f;
    p = fmaf(p, f, 1.3981999507e-3f);
    p = fmaf(p, f, 8.3334519073e-3f);
    p = fmaf(p, f, 4.1665795894e-2f);
    p = fmaf(p, f, 1.6666665459e-1f);
    p = fmaf(p, f, 5.0000001201e-1f);
    float zz = f * f;
    float e = fmaf(p, zz, f) + 1.0f;
    return __int_as_float(__float_as_int(e) + (ti << 23));
}

// ---------------------------------------------------------------------------
// K1: M = u @ tinyW (20000x256, K=64) with packed f32x2 FMA, softmax over 256,
//     zpre = ln10 + clamp(logsoftmax). Transpose via smem.
//     IDEMPOTENT — launched 2x this round: k1 = dur delta vs single launch.
// ---------------------------------------------------------------------------
__global__ void __launch_bounds__(256) k1_gemm(const float* __restrict__ u,
                                               const float* __restrict__ tinyW) {
    __shared__ float zs[32 * 258];
    const int t = threadIdx.x, lane = t & 31, w = t >> 5;
    const int n0 = blockIdx.x * 32;
    const int fb = n0 + w * 4;

    unsigned long long acc2[4][4];
#pragma unroll
    for (int j = 0; j < 4; j++)
#pragma unroll
        for (int i = 0; i < 4; i++) acc2[j][i] = 0ull;

    const float2* tw2 = reinterpret_cast<const float2*>(tinyW);
#pragma unroll 1
    for (int k = 0; k < KD; k += 4) {
        float4 uv[4];
#pragma unroll
        for (int i = 0; i < 4; i++)
            uv[i] = *reinterpret_cast<const float4*>(u + (size_t)(fb + i) * KD + k);
#pragma unroll
        for (int kk = 0; kk < 4; kk++) {
            unsigned long long wp[4];
#pragma unroll
            for (int j = 0; j < 4; j++) {
                float2 wv = __ldg(&tw2[(size_t)(k + kk) * 128 + j * 32 + lane]);
                asm("mov.b64 %0, {%1, %2};" : "=l"(wp[j]) : "f"(wv.x), "f"(wv.y));
            }
#pragma unroll
            for (int i = 0; i < 4; i++) {
                float uk = (kk == 0) ? uv[i].x : (kk == 1) ? uv[i].y
                         : (kk == 2) ? uv[i].z : uv[i].w;
                unsigned long long up;
                asm("mov.b64 %0, {%1, %1};" : "=l"(up) : "f"(uk));
#pragma unroll
                for (int j = 0; j < 4; j++)
                    asm("fma.rn.f32x2 %0, %1, %2, %0;"
                        : "+l"(acc2[j][i]) : "l"(up), "l"(wp[j]));
            }
        }
    }

    const float LN10  = 2.302585092994046f;
    const float LNEPS = -16.118095650958319f;
    const float LNHI  = -1.0000000500000026e-7f;
#pragma unroll
    for (int i = 0; i < 4; i++) {
        float v[8];
#pragma unroll
        for (int j = 0; j < 4; j++)
            asm("mov.b64 {%0, %1}, %2;" : "=f"(v[2*j]), "=f"(v[2*j+1]) : "l"(acc2[j][i]));
        float m = v[0];
#pragma unroll
        for (int j = 1; j < 8; j++) m = fmaxf(m, v[j]);
#pragma unroll
        for (int o = 16; o; o >>= 1) m = fmaxf(m, __shfl_xor_sync(0xffffffffu, m, o));
        float s = 0.f;
#pragma unroll
        for (int j = 0; j < 8; j++) s += fast_exp(v[j] - m);
#pragma unroll
        for (int o = 16; o; o >>= 1) s += __shfl_xor_sync(0xffffffffu, s, o);
        float lns = fast_log(s);
        float2* zrow = reinterpret_cast<float2*>(zs + (w * 4 + i) * 258);
#pragma unroll
        for (int j = 0; j < 4; j++) {
            float z0 = LN10 + fminf(fmaxf(v[2*j]   - m - lns, LNEPS), LNHI);
            float z1 = LN10 + fminf(fmaxf(v[2*j+1] - m - lns, LNEPS), LNHI);
            zrow[j * 32 + lane] = make_float2(z0, z1);
        }
    }
    __syncthreads();
    const int tx = t & 31, ty = t >> 5;
#pragma unroll 4
    for (int dd = ty; dd < DOUT; dd += 8)
        g_Z[(size_t)dd * NFEAT + n0 + tx] = zs[tx * 258 + dd];
}

// ---------------------------------------------------------------------------
// K3: one CTA per row d, 384 threads (2 CTAs/SM without reg cap -> one wave).
//     Values computed once into smem zv[20000]; exact 256th-largest via
//     3-level radix select (lvl0 fused into compute pass, lvl1 into sumexp).
//     Sort replaced by rank-placement: keys strictly distinct, one barrier.
// ---------------------------------------------------------------------------
#define K3_THREADS 384
#define K3_DSMEM (80000 + 8192 + 8192)   // zv + histA[2048] + histB[2048]

// warp-0 top-down suffix scan over hist[nb]: find bucket of the kk-th largest
__device__ __forceinline__ void suffix_scan(const uint32_t* hist, int nb, int lane,
                                            uint32_t kk, uint32_t* s_b, uint32_t* s_knew) {
    const int chunk = nb >> 5;
    const int base = nb - 1 - lane * chunk;
    uint32_t S = 0;
    for (int j = 0; j < chunk; j++) S += hist[base - j];
    uint32_t cum = S;
#pragma unroll
    for (int o = 1; o < 32; o <<= 1) {
        uint32_t vv = __shfl_up_sync(0xffffffffu, cum, o);
        if (lane >= o) cum += vv;
    }
    uint32_t excl = cum - S;
    if (excl < kk && excl + S >= kk) {
        uint32_t c2 = excl;
        for (int j = 0; j < chunk; j++) {
            uint32_t h = hist[base - j];
            if (c2 + h >= kk) { *s_b = (uint32_t)(base - j); *s_knew = kk - c2; break; }
            c2 += h;
        }
    }
}

__global__ void __launch_bounds__(K3_THREADS) k3_select(const float* __restrict__ uniform) {
    extern __shared__ unsigned char dyn[];
    uint32_t* zv = reinterpret_cast<uint32_t*>(dyn);               // 20000 u32
    uint32_t* hA = reinterpret_cast<uint32_t*>(dyn + 80000);       // 2048 (lvl 0 / lvl 2)
    uint32_t* hB = reinterpret_cast<uint32_t*>(dyn + 88192);       // 2048 (lvl 1)
    unsigned long long* skey = reinterpret_cast<unsigned long long*>(dyn + 80000);

    __shared__ uint32_t shu[12];
    __shared__ float    shf[12];
    __shared__ uint32_t s_b, s_knew;
    __shared__ int      s_cnt;

    const int d = blockIdx.x;
    const int t = threadIdx.x, lane = t & 31, w = t >> 5;   // 12 warps
    const float invt = 1.0f / 9.9999f;            // temp = max(0.1, 10*0.99999)

    for (int i = t; i < 2048; i += K3_THREADS) { hA[i] = 0u; hB[i] = 0u; }
    __syncthreads();

    // ---- pass 1: compute mapped values + level-0 histogram + row max ----
    const float4* Z4 = reinterpret_cast<const float4*>(g_Z + (size_t)d * NFEAT);
    const float4* U4 = reinterpret_cast<const float4*>(uniform + (size_t)d * NFEAT);
    uint32_t mmax = 0;
#pragma unroll
    for (int i = 0; i < 14; i++) {
        int q = i * K3_THREADS + t;
        if (q < NFEAT / 4) {
            float4 zp = Z4[q], uu = U4[q];
            uint32_t m0 = f2o((zp.x - fast_log(-fast_log(uu.x))) * invt);
            uint32_t m1 = f2o((zp.y - fast_log(-fast_log(uu.y))) * invt);
            uint32_t m2 = f2o((zp.z - fast_log(-fast_log(uu.z))) * invt);
            uint32_t m3 = f2o((zp.w - fast_log(-fast_log(uu.w))) * invt);
            zv[4*q+0] = m0; zv[4*q+1] = m1; zv[4*q+2] = m2; zv[4*q+3] = m3;
            atomicAdd(&hA[m0 >> 21], 1u);
            atomicAdd(&hA[m1 >> 21], 1u);
            atomicAdd(&hA[m2 >> 21], 1u);
            atomicAdd(&hA[m3 >> 21], 1u);
            mmax = max(mmax, max(max(m0, m1), max(m2, m3)));
        }
    }
#pragma unroll
    for (int o = 16; o; o >>= 1) mmax = max(mmax, __shfl_xor_sync(0xffffffffu, mmax, o));
    if (lane == 0) shu[w] = mmax;
    __syncthreads();                               // hA complete, shu visible
    uint32_t rmax_m = shu[0];
#pragma unroll
    for (int i = 1; i < 12; i++) rmax_m = max(rmax_m, shu[i]);
    const float rowmax = o2f(rmax_m);

    // ---- level-0 scan ----
    if (t < 32) suffix_scan(hA, 2048, lane, 256u, &s_b, &s_knew);
    __syncthreads();
    const uint32_t p0 = s_b;                       // top 11 bits
    const uint32_t kk1 = s_knew;

    // ---- pass 2: sumexp + level-1 histogram (fused) + re-zero hA ----
    for (int i = t; i < 1024; i += K3_THREADS) hA[i] = 0u;   // for level 2
    float ls = 0.f;
    for (int n = t; n < NFEAT; n += K3_THREADS) {
        uint32_t v = zv[n];
        ls += fast_exp(o2f(v) - rowmax);
        if ((v >> 21) == p0) atomicAdd(&hB[(v >> 10) & 2047], 1u);
    }
#pragma unroll
    for (int o = 16; o; o >>= 1) ls += __shfl_xor_sync(0xffffffffu, ls, o);
    if (lane == 0) shf[w] = ls;
    __syncthreads();                               // hB complete, hA zeroed, shf visible
    float ssum = 0.f;
#pragma unroll
    for (int i = 0; i < 12; i++) ssum += shf[i];
    const float c = rowmax + fast_log(ssum);       // logsumexp offset

    // ---- level-1 scan ----
    if (t < 32) suffix_scan(hB, 2048, lane, kk1, &s_b, &s_knew);
    __syncthreads();
    const uint32_t p22 = (p0 << 11) | s_b;         // top 22 bits
    const uint32_t kk2 = s_knew;

    // ---- pass 3: level-2 histogram ----
    for (int n = t; n < NFEAT; n += K3_THREADS) {
        uint32_t v = zv[n];
        if ((v >> 10) == p22) atomicAdd(&hA[v & 1023], 1u);
    }
    __syncthreads();
    if (t < 32) suffix_scan(hA, 1024, lane, kk2, &s_b, &s_knew);
    __syncthreads();
    const uint32_t thr = (p22 << 10) | s_b;        // exact 256th-largest value

    // ---- collect candidates >= thr ----
    if (t == 0) s_cnt = 0;
    __syncthreads();
    for (int n = t; n < NFEAT; n += K3_THREADS) {
        uint32_t v = zv[n];
        if (v >= thr) {
            int p = atomicAdd(&s_cnt, 1);
            if (p < 512)
                skey[p] = ((unsigned long long)v << 32) | (uint32_t)(NFEAT - n);
        }
    }
    __syncthreads();
    int cnt = s_cnt; if (cnt > 512) cnt = 512;

    // ---- rank placement (replaces bitonic sort): keys strictly distinct
    //      ((val, NFEAT-n) pack), rank = #{j: key_j > key_i} is a permutation.
    //      Desc value, asc index — same order as the old sort. One barrier.
    for (int i = t; i < cnt; i += K3_THREADS) {
        unsigned long long ki = skey[i];
        int rank = 0;
        for (int j = 0; j < cnt; j++) rank += (skey[j] > ki) ? 1 : 0;
        if (rank < 256) {
            float val = o2f((uint32_t)(ki >> 32)) - c;     // log-softmax value
            uint32_t idx = (uint32_t)(NFEAT - (int)(ki & 0xffffffffu));
            g_pack[d * 256 + rank] = ((unsigned long long)f2o(val) << 32) | idx;
        }
    }
}

// ---------------------------------------------------------------------------
// K4: EXACT batch-dominant greedy matching (R10 win: ~5us). Thread = row.
// ---------------------------------------------------------------------------
#define K4_DSMEM (NFEAT * 8)                        // colbest[20000] u64 = 160 KB

__global__ void __launch_bounds__(256) k4_greedy() {
    extern __shared__ unsigned long long colbest[]; // [NFEAT]
    __shared__ uint32_t used[(NFEAT + 31) / 32];
    __shared__ unsigned long long sL;
    const int t = threadIdx.x;

    for (int i = t; i < (NFEAT + 31) / 32; i += 256) used[i] = 0u;

    unsigned long long pk = __ldg(&g_pack[t * 256]);
    unsigned long long key = (pk & 0xffffffff00000000ull) | (uint32_t)(255 - t);
    int col = (int)(uint32_t)pk;
    int ptr = 0;
    int active = 1;
    int remaining = DOUT;

    while (remaining > 0) {
        if (active) colbest[col] = 0ull;            // clear only touched cols
        if (t == 0) sL = 0ull;
        __syncthreads();
        if (active) atomicMax(&colbest[col], key);
        __syncthreads();
        const int winner = active && (colbest[col] == key);
        if (active && !winner) atomicMax(&sL, key); // losers raise the bar
        __syncthreads();
        const unsigned long long L = sL;
        int acc = 0;
        if (winner && key > L) {                    // safe accept
            g_sel[t] = col;
            atomicOr(&used[col >> 5], 1u << (col & 31));
            active = 0;
            acc = 1;
        }
        const int n = __syncthreads_count(acc);     // barrier + count accepted
        remaining -= n;
        if (active && ((used[col >> 5] >> (col & 31)) & 1u)) {
            do {                                    // advance past used cols
                ptr++;
                pk = __ldg(&g_pack[t * 256 + ptr]);
                col = (int)(uint32_t)pk;
            } while (ptr < 255 && ((used[col >> 5] >> (col & 31)) & 1u));
            key = (pk & 0xffffffff00000000ull) | (uint32_t)(255 - t);
        }
        __syncthreads();
    }
}

// ---------------------------------------------------------------------------
// K5: Y[b,d] = X[b, sel[d]] — gather, L2-only loads, 8 rows/thread, grid 512.
//     With 32B fetch granularity k5 is latency-bound (occ 21%, DRAM 27%):
//     double the CTAs to double resident warps / in-flight loads.
// ---------------------------------------------------------------------------
__global__ void __launch_bounds__(256) k5_gather(const float* __restrict__ X,
                                                 float* __restrict__ Y) {
    __shared__ int scol[256];
    scol[threadIdx.x] = g_sel[threadIdx.x];
    __syncthreads();
    const int b0 = blockIdx.x * 8;
    const int dd = threadIdx.x;
    const int c = scol[dd];
    float v[8];
#pragma unroll
    for (int j = 0; j < 8; j++)
        v[j] = __ldcg(X + (size_t)(b0 + j) * NFEAT + c);
#pragma unroll
    for (int j = 0; j < 8; j++)
        Y[(size_t)(b0 + j) * DOUT + dd] = v[j];
}

// ---------------------------------------------------------------------------
extern "C" void kernel_launch(void* const* d_in, const int* in_sizes, int n_in,
                              void* d_out, int out_size) {
    const float* X       = (const float*)d_in[0];   // (4096, 20000)
    const float* u       = (const float*)d_in[1];   // (20000, 64)
    const float* tinyW   = (const float*)d_in[2];   // (64, 256)
    const float* uniform = (const float*)d_in[3];   // (256, 20000)
    float* Y = (float*)d_out;                       // (4096, 256)

    static bool attr_done = false;
    if (!attr_done) {
        cudaFuncSetAttribute(k3_select,
                             cudaFuncAttributeMaxDynamicSharedMemorySize, K3_DSMEM);
        cudaFuncSetAttribute(k4_greedy,
                             cudaFuncAttributeMaxDynamicSharedMemorySize, K4_DSMEM);
        // scattered 4B gathers in k5: fetch 32B sectors, not 128B lines
        cudaDeviceSetLimit(cudaLimitMaxL2FetchGranularity, 32);
        attr_done = true;
    }

    // ATTRIBUTION: k1 is idempotent; 2 launches => dur delta vs single = k1.
    k1_gemm  <<<NFEAT / 32, 256>>>(u, tinyW);
    k1_gemm  <<<NFEAT / 32, 256>>>(u, tinyW);
    k3_select<<<DOUT, K3_THREADS, K3_DSMEM>>>(uniform);
    k4_greedy<<<1, 256, K4_DSMEM>>>();
    k5_gather<<<BATCH / 8, 256>>>(X, Y);
}

// round 14
// speedup vs baseline: 1.4758x; 1.4758x over previous
#include <cuda_runtime.h>
#include <cstdint>

#define NFEAT 20000
#define DOUT  256
#define BATCH 4096
#define KD    64

// ---------------- scratch (static device globals; no runtime allocation) ----
__device__ float g_Z[(size_t)DOUT * NFEAT];              // zpre[d][n]
__device__ unsigned long long g_pack[DOUT * 256];        // (f2o(val)<<32)|idx, desc per row
__device__ int   g_sel[DOUT];                            // selected column per row d

// orderable-uint mapping for floats (monotone increasing)
__device__ __forceinline__ uint32_t f2o(float f) {
    uint32_t b = __float_as_uint(f);
    return (b & 0x80000000u) ? ~b : (b | 0x80000000u);
}
__device__ __forceinline__ float o2f(uint32_t m) {
    uint32_t b = (m & 0x80000000u) ? (m & 0x7fffffffu) : ~m;
    return __uint_as_float(b);
}

// ---------------- FFMA-only transcendentals (no MUFU, ~1-2 ulp) -------------
__device__ __forceinline__ float fast_log(float x) {      // x normal, > 0
    int i = __float_as_int(x);
    int e = (i - 0x3f3504f3) & 0xff800000;
    float m = __int_as_float(i - e);
    float fe = (float)(e >> 23);
    float f = m - 1.0f;
    float z = f * f;
    float p = 7.0376836292e-2f;
    p = fmaf(p, f, -1.1514610310e-1f);
    p = fmaf(p, f,  1.1676998740e-1f);
    p = fmaf(p, f, -1.2420140846e-1f);
    p = fmaf(p, f,  1.4249322787e-1f);
    p = fmaf(p, f, -1.6668057665e-1f);
    p = fmaf(p, f,  2.0000714765e-1f);
    p = fmaf(p, f, -2.4999993993e-1f);
    p = fmaf(p, f,  3.3333331174e-1f);
    float y = p * f * z;
    y = fmaf(fe, -2.12194440e-4f, y);
    y = fmaf(-0.5f, z, y);
    float r = f + y;
    return fmaf(fe, 0.693359375f, r);
}

__device__ __forceinline__ float fast_exp(float x) {      // |x| < ~80
    const float LOG2E = 1.4426950408889634f;
    float fr = fmaf(x, LOG2E, 12582912.0f);
    int ti = __float_as_int(fr) - 0x4B400000;
    float r = fr - 12582912.0f;
    float f = fmaf(r, -0.693359375f, x);
    f = fmaf(r, 2.12194440e-4f, f);
    float p = 1.9875691500e-4f;
    p = fmaf(p, f, 1.3981999507e-3f);
    p = fmaf(p, f, 8.3334519073e-3f);
    p = fmaf(p, f, 4.1665795894e-2f);
    p = fmaf(p, f, 1.6666665459e-1f);
    p = fmaf(p, f, 5.0000001201e-1f);
    float zz = f * f;
    float e = fmaf(p, zz, f) + 1.0f;
    return __int_as_float(__float_as_int(e) + (ti << 23));
}

// ---------------------------------------------------------------------------
// K1: M = u @ tinyW (20000x256, K=64), softmax over 256, zpre via smem.
//     v2: tinyW staged in dynamic smem ONCE per CTA (R13 showed k1 ~29us,
//     LDG-issue-bound: 272 LDG/thread). Mainloop reads tinyW via LDS.64
//     (conflict-free), cutting per-thread LDG to 80. The transpose buffer
//     zs ALIASES the tinyW smem (barrier-separated) so smem stays 64KB.
// ---------------------------------------------------------------------------
#define K1_DSMEM 65536    // max(64KB tinyW, 33KB zs)

__global__ void __launch_bounds__(256) k1_gemm(const float* __restrict__ u,
                                               const float* __restrict__ tinyW) {
    extern __shared__ float k1dyn[];
    float2* sW2 = reinterpret_cast<float2*>(k1dyn);   // [64][128] float2 view
    float*  zs  = k1dyn;                              // aliased post-barrier
    const int t = threadIdx.x, lane = t & 31, w = t >> 5;
    const int n0 = blockIdx.x * 32;
    const int fb = n0 + w * 4;

    // stage tinyW (64x256 f32 = 4096 float4) into smem, coalesced
    {
        const float4* tw4 = reinterpret_cast<const float4*>(tinyW);
        float4* sW4 = reinterpret_cast<float4*>(k1dyn);
#pragma unroll
        for (int i = 0; i < 16; i++)
            sW4[i * 256 + t] = tw4[i * 256 + t];
    }
    __syncthreads();

    unsigned long long acc2[4][4];
#pragma unroll
    for (int j = 0; j < 4; j++)
#pragma unroll
        for (int i = 0; i < 4; i++) acc2[j][i] = 0ull;

#pragma unroll 1
    for (int k = 0; k < KD; k += 4) {
        float4 uv[4];
#pragma unroll
        for (int i = 0; i < 4; i++)
            uv[i] = *reinterpret_cast<const float4*>(u + (size_t)(fb + i) * KD + k);
#pragma unroll
        for (int kk = 0; kk < 4; kk++) {
            unsigned long long wp[4];
#pragma unroll
            for (int j = 0; j < 4; j++) {
                float2 wv = sW2[(k + kk) * 128 + j * 32 + lane];   // LDS.64
                asm("mov.b64 %0, {%1, %2};" : "=l"(wp[j]) : "f"(wv.x), "f"(wv.y));
            }
#pragma unroll
            for (int i = 0; i < 4; i++) {
                float uk = (kk == 0) ? uv[i].x : (kk == 1) ? uv[i].y
                         : (kk == 2) ? uv[i].z : uv[i].w;
                unsigned long long up;
                asm("mov.b64 %0, {%1, %1};" : "=l"(up) : "f"(uk));
#pragma unroll
                for (int j = 0; j < 4; j++)
                    asm("fma.rn.f32x2 %0, %1, %2, %0;"
                        : "+l"(acc2[j][i]) : "l"(up), "l"(wp[j]));
            }
        }
    }
    __syncthreads();   // ALL tinyW smem reads done before zs overwrites it

    const float LN10  = 2.302585092994046f;
    const float LNEPS = -16.118095650958319f;
    const float LNHI  = -1.0000000500000026e-7f;
#pragma unroll
    for (int i = 0; i < 4; i++) {
        float v[8];
#pragma unroll
        for (int j = 0; j < 4; j++)
            asm("mov.b64 {%0, %1}, %2;" : "=f"(v[2*j]), "=f"(v[2*j+1]) : "l"(acc2[j][i]));
        float m = v[0];
#pragma unroll
        for (int j = 1; j < 8; j++) m = fmaxf(m, v[j]);
#pragma unroll
        for (int o = 16; o; o >>= 1) m = fmaxf(m, __shfl_xor_sync(0xffffffffu, m, o));
        float s = 0.f;
#pragma unroll
        for (int j = 0; j < 8; j++) s += fast_exp(v[j] - m);
#pragma unroll
        for (int o = 16; o; o >>= 1) s += __shfl_xor_sync(0xffffffffu, s, o);
        float lns = fast_log(s);
        float2* zrow = reinterpret_cast<float2*>(zs + (w * 4 + i) * 258);
#pragma unroll
        for (int j = 0; j < 4; j++) {
            float z0 = LN10 + fminf(fmaxf(v[2*j]   - m - lns, LNEPS), LNHI);
            float z1 = LN10 + fminf(fmaxf(v[2*j+1] - m - lns, LNEPS), LNHI);
            zrow[j * 32 + lane] = make_float2(z0, z1);
        }
    }
    __syncthreads();
    const int tx = t & 31, ty = t >> 5;
#pragma unroll 4
    for (int dd = ty; dd < DOUT; dd += 8)
        g_Z[(size_t)dd * NFEAT + n0 + tx] = zs[tx * 258 + dd];
}

// ---------------------------------------------------------------------------
// K3: one CTA per row d, 384 threads (2 CTAs/SM, one wave). Values computed
//     once into smem zv[20000]; exact 256th-largest via 3-level radix select
//     (lvl0 fused into compute pass, lvl1 into sumexp). Rank placement.
// ---------------------------------------------------------------------------
#define K3_THREADS 384
#define K3_DSMEM (80000 + 8192 + 8192)   // zv + histA[2048] + histB[2048]

// warp-0 top-down suffix scan over hist[nb]: find bucket of the kk-th largest
__device__ __forceinline__ void suffix_scan(const uint32_t* hist, int nb, int lane,
                                            uint32_t kk, uint32_t* s_b, uint32_t* s_knew) {
    const int chunk = nb >> 5;
    const int base = nb - 1 - lane * chunk;
    uint32_t S = 0;
    for (int j = 0; j < chunk; j++) S += hist[base - j];
    uint32_t cum = S;
#pragma unroll
    for (int o = 1; o < 32; o <<= 1) {
        uint32_t vv = __shfl_up_sync(0xffffffffu, cum, o);
        if (lane >= o) cum += vv;
    }
    uint32_t excl = cum - S;
    if (excl < kk && excl + S >= kk) {
        uint32_t c2 = excl;
        for (int j = 0; j < chunk; j++) {
            uint32_t h = hist[base - j];
            if (c2 + h >= kk) { *s_b = (uint32_t)(base - j); *s_knew = kk - c2; break; }
            c2 += h;
        }
    }
}

__global__ void __launch_bounds__(K3_THREADS) k3_select(const float* __restrict__ uniform) {
    extern __shared__ unsigned char dyn[];
    uint32_t* zv = reinterpret_cast<uint32_t*>(dyn);               // 20000 u32
    uint32_t* hA = reinterpret_cast<uint32_t*>(dyn + 80000);       // 2048 (lvl 0 / lvl 2)
    uint32_t* hB = reinterpret_cast<uint32_t*>(dyn + 88192);       // 2048 (lvl 1)
    unsigned long long* skey = reinterpret_cast<unsigned long long*>(dyn + 80000);

    __shared__ uint32_t shu[12];
    __shared__ float    shf[12];
    __shared__ uint32_t s_b, s_knew;
    __shared__ int      s_cnt;

    const int d = blockIdx.x;
    const int t = threadIdx.x, lane = t & 31, w = t >> 5;   // 12 warps
    const float invt = 1.0f / 9.9999f;            // temp = max(0.1, 10*0.99999)

    for (int i = t; i < 2048; i += K3_THREADS) { hA[i] = 0u; hB[i] = 0u; }
    __syncthreads();

    // ---- pass 1: compute mapped values + level-0 histogram + row max ----
    const float4* Z4 = reinterpret_cast<const float4*>(g_Z + (size_t)d * NFEAT);
    const float4* U4 = reinterpret_cast<const float4*>(uniform + (size_t)d * NFEAT);
    uint32_t mmax = 0;
#pragma unroll
    for (int i = 0; i < 14; i++) {
        int q = i * K3_THREADS + t;
        if (q < NFEAT / 4) {
            float4 zp = Z4[q], uu = U4[q];
            uint32_t m0 = f2o((zp.x - fast_log(-fast_log(uu.x))) * invt);
            uint32_t m1 = f2o((zp.y - fast_log(-fast_log(uu.y))) * invt);
            uint32_t m2 = f2o((zp.z - fast_log(-fast_log(uu.z))) * invt);
            uint32_t m3 = f2o((zp.w - fast_log(-fast_log(uu.w))) * invt);
            zv[4*q+0] = m0; zv[4*q+1] = m1; zv[4*q+2] = m2; zv[4*q+3] = m3;
            atomicAdd(&hA[m0 >> 21], 1u);
            atomicAdd(&hA[m1 >> 21], 1u);
            atomicAdd(&hA[m2 >> 21], 1u);
            atomicAdd(&hA[m3 >> 21], 1u);
            mmax = max(mmax, max(max(m0, m1), max(m2, m3)));
        }
    }
#pragma unroll
    for (int o = 16; o; o >>= 1) mmax = max(mmax, __shfl_xor_sync(0xffffffffu, mmax, o));
    if (lane == 0) shu[w] = mmax;
    __syncthreads();                               // hA complete, shu visible
    uint32_t rmax_m = shu[0];
#pragma unroll
    for (int i = 1; i < 12; i++) rmax_m = max(rmax_m, shu[i]);
    const float rowmax = o2f(rmax_m);

    // ---- level-0 scan ----
    if (t < 32) suffix_scan(hA, 2048, lane, 256u, &s_b, &s_knew);
    __syncthreads();
    const uint32_t p0 = s_b;                       // top 11 bits
    const uint32_t kk1 = s_knew;

    // ---- pass 2: sumexp + level-1 histogram (fused) + re-zero hA ----
    for (int i = t; i < 1024; i += K3_THREADS) hA[i] = 0u;   // for level 2
    float ls = 0.f;
    for (int n = t; n < NFEAT; n += K3_THREADS) {
        uint32_t v = zv[n];
        ls += fast_exp(o2f(v) - rowmax);
        if ((v >> 21) == p0) atomicAdd(&hB[(v >> 10) & 2047], 1u);
    }
#pragma unroll
    for (int o = 16; o; o >>= 1) ls += __shfl_xor_sync(0xffffffffu, ls, o);
    if (lane == 0) shf[w] = ls;
    __syncthreads();                               // hB complete, hA zeroed, shf visible
    float ssum = 0.f;
#pragma unroll
    for (int i = 0; i < 12; i++) ssum += shf[i];
    const float c = rowmax + fast_log(ssum);       // logsumexp offset

    // ---- level-1 scan ----
    if (t < 32) suffix_scan(hB, 2048, lane, kk1, &s_b, &s_knew);
    __syncthreads();
    const uint32_t p22 = (p0 << 11) | s_b;         // top 22 bits
    const uint32_t kk2 = s_knew;

    // ---- pass 3: level-2 histogram ----
    for (int n = t; n < NFEAT; n += K3_THREADS) {
        uint32_t v = zv[n];
        if ((v >> 10) == p22) atomicAdd(&hA[v & 1023], 1u);
    }
    __syncthreads();
    if (t < 32) suffix_scan(hA, 1024, lane, kk2, &s_b, &s_knew);
    __syncthreads();
    const uint32_t thr = (p22 << 10) | s_b;        // exact 256th-largest value

    // ---- collect candidates >= thr ----
    if (t == 0) s_cnt = 0;
    __syncthreads();
    for (int n = t; n < NFEAT; n += K3_THREADS) {
        uint32_t v = zv[n];
        if (v >= thr) {
            int p = atomicAdd(&s_cnt, 1);
            if (p < 512)
                skey[p] = ((unsigned long long)v << 32) | (uint32_t)(NFEAT - n);
        }
    }
    __syncthreads();
    int cnt = s_cnt; if (cnt > 512) cnt = 512;

    // ---- rank placement: keys strictly distinct ((val, NFEAT-n) pack),
    //      rank = #{j: key_j > key_i}. Desc value, asc index. One barrier.
    for (int i = t; i < cnt; i += K3_THREADS) {
        unsigned long long ki = skey[i];
        int rank = 0;
        for (int j = 0; j < cnt; j++) rank += (skey[j] > ki) ? 1 : 0;
        if (rank < 256) {
            float val = o2f((uint32_t)(ki >> 32)) - c;     // log-softmax value
            uint32_t idx = (uint32_t)(NFEAT - (int)(ki & 0xffffffffu));
            g_pack[d * 256 + rank] = ((unsigned long long)f2o(val) << 32) | idx;
        }
    }
}

// ---------------------------------------------------------------------------
// K4: EXACT batch-dominant greedy matching (measured 5.4us). Thread = row.
// ---------------------------------------------------------------------------
#define K4_DSMEM (NFEAT * 8)                        // colbest[20000] u64 = 160 KB

__global__ void __launch_bounds__(256) k4_greedy() {
    extern __shared__ unsigned long long colbest[]; // [NFEAT]
    __shared__ uint32_t used[(NFEAT + 31) / 32];
    __shared__ unsigned long long sL;
    const int t = threadIdx.x;

    for (int i = t; i < (NFEAT + 31) / 32; i += 256) used[i] = 0u;

    unsigned long long pk = __ldg(&g_pack[t * 256]);
    unsigned long long key = (pk & 0xffffffff00000000ull) | (uint32_t)(255 - t);
    int col = (int)(uint32_t)pk;
    int ptr = 0;
    int active = 1;
    int remaining = DOUT;

    while (remaining > 0) {
        if (active) colbest[col] = 0ull;            // clear only touched cols
        if (t == 0) sL = 0ull;
        __syncthreads();
        if (active) atomicMax(&colbest[col], key);
        __syncthreads();
        const int winner = active && (colbest[col] == key);
        if (active && !winner) atomicMax(&sL, key); // losers raise the bar
        __syncthreads();
        const unsigned long long L = sL;
        int acc = 0;
        if (winner && key > L) {                    // safe accept
            g_sel[t] = col;
            atomicOr(&used[col >> 5], 1u << (col & 31));
            active = 0;
            acc = 1;
        }
        const int n = __syncthreads_count(acc);     // barrier + count accepted
        remaining -= n;
        if (active && ((used[col >> 5] >> (col & 31)) & 1u)) {
            do {                                    // advance past used cols
                ptr++;
                pk = __ldg(&g_pack[t * 256 + ptr]);
                col = (int)(uint32_t)pk;
            } while (ptr < 255 && ((used[col >> 5] >> (col & 31)) & 1u));
            key = (pk & 0xffffffff00000000ull) | (uint32_t)(255 - t);
        }
        __syncthreads();
    }
}

// ---------------------------------------------------------------------------
// K5: Y[b,d] = X[b, sel[d]] — gather, L2-only loads, 16 rows/thread, grid 256
//     (R12-measured 16.6us with 32B fetch granularity).
// ---------------------------------------------------------------------------
__global__ void __launch_bounds__(256) k5_gather(const float* __restrict__ X,
                                                 float* __restrict__ Y) {
    __shared__ int scol[256];
    scol[threadIdx.x] = g_sel[threadIdx.x];
    __syncthreads();
    const int b0 = blockIdx.x * 16;
    const int dd = threadIdx.x;
    const int c = scol[dd];
    float v[16];
#pragma unroll
    for (int j = 0; j < 16; j++)
        v[j] = __ldcg(X + (size_t)(b0 + j) * NFEAT + c);
#pragma unroll
    for (int j = 0; j < 16; j++)
        Y[(size_t)(b0 + j) * DOUT + dd] = v[j];
}

// ---------------------------------------------------------------------------
extern "C" void kernel_launch(void* const* d_in, const int* in_sizes, int n_in,
                              void* d_out, int out_size) {
    const float* X       = (const float*)d_in[0];   // (4096, 20000)
    const float* u       = (const float*)d_in[1];   // (20000, 64)
    const float* tinyW   = (const float*)d_in[2];   // (64, 256)
    const float* uniform = (const float*)d_in[3];   // (256, 20000)
    float* Y = (float*)d_out;                       // (4096, 256)

    static bool attr_done = false;
    if (!attr_done) {
        cudaFuncSetAttribute(k1_gemm,
                             cudaFuncAttributeMaxDynamicSharedMemorySize, K1_DSMEM);
        cudaFuncSetAttribute(k3_select,
                             cudaFuncAttributeMaxDynamicSharedMemorySize, K3_DSMEM);
        cudaFuncSetAttribute(k4_greedy,
                             cudaFuncAttributeMaxDynamicSharedMemorySize, K4_DSMEM);
        // scattered 4B gathers in k5: fetch 32B sectors, not 128B lines
        cudaDeviceSetLimit(cudaLimitMaxL2FetchGranularity, 32);
        attr_done = true;
    }

    k1_gemm  <<<NFEAT / 32, 256, K1_DSMEM>>>(u, tinyW);
    k3_select<<<DOUT, K3_THREADS, K3_DSMEM>>>(uniform);
    k4_greedy<<<1, 256, K4_DSMEM>>>();
    k5_gather<<<BATCH / 16, 256>>>(X, Y);
}